// round 1
// baseline (speedup 1.0000x reference)
#include <cuda_runtime.h>
#include <math.h>

#define N_PROP 1024
#define C_ALL 81
#define CF 80
#define DET 100
#define SCORE_THRESH 0.05f
#define NMS_THRESH 0.5f
#define IMG_W 1333.0f
#define IMG_H 800.0f
#define KEEP_CAP 32768
#define SORTN 4096

// Scratch (allocation-free: __device__ globals)
__device__ float g_scores[CF * N_PROP];
__device__ float4 g_boxes[CF * N_PROP];
__device__ unsigned long long g_keep_key[KEEP_CAP];
__device__ float4 g_keep_box[KEEP_CAP];
__device__ int g_keep_count;

// ---------------------------------------------------------------------------
// K1: softmax over 81 classes + BoxCoder decode + clip. One block per proposal.
// ---------------------------------------------------------------------------
__global__ void k1_decode(const float* __restrict__ logits,
                          const float* __restrict__ rel,
                          const float* __restrict__ props) {
    int n = blockIdx.x;
    int t = threadIdx.x;
    if (n == 0 && t == 0) g_keep_count = 0;

    __shared__ float red[128];
    float v = (t < C_ALL) ? logits[n * C_ALL + t] : -1e30f;
    red[t] = v;
    __syncthreads();
    for (int s = 64; s > 0; s >>= 1) {
        if (t < s) red[t] = fmaxf(red[t], red[t + s]);
        __syncthreads();
    }
    float mx = red[0];
    __syncthreads();
    float e = (t < C_ALL) ? expf(v - mx) : 0.f;
    red[t] = e;
    __syncthreads();
    for (int s = 64; s > 0; s >>= 1) {
        if (t < s) red[t] += red[t + s];
        __syncthreads();
    }
    float sum = red[0];

    if (t >= 1 && t < C_ALL) {
        float prob = e / sum;

        float bx1 = props[n * 4 + 0], by1 = props[n * 4 + 1];
        float bx2 = props[n * 4 + 2], by2 = props[n * 4 + 3];
        float w = bx2 - bx1 + 1.0f, h = by2 - by1 + 1.0f;
        float cx = bx1 + 0.5f * w, cy = by1 + 0.5f * h;

        const float CLIP = 4.135166556742356f;  // log(1000/16)
        const float* r4 = rel + n * (4 * C_ALL) + 4 * t;
        float dx = r4[0] / 10.0f;
        float dy = r4[1] / 10.0f;
        float dw = fminf(r4[2] / 5.0f, CLIP);
        float dh = fminf(r4[3] / 5.0f, CLIP);

        float pcx = dx * w + cx, pcy = dy * h + cy;
        float pw = expf(dw) * w, ph = expf(dh) * h;
        float x1 = pcx - 0.5f * pw;
        float y1 = pcy - 0.5f * ph;
        float x2 = pcx + 0.5f * pw - 1.0f;
        float y2 = pcy + 0.5f * ph - 1.0f;

        x1 = fminf(fmaxf(x1, 0.f), IMG_W - 1.f);
        x2 = fminf(fmaxf(x2, 0.f), IMG_W - 1.f);
        y1 = fminf(fmaxf(y1, 0.f), IMG_H - 1.f);
        y2 = fminf(fmaxf(y2, 0.f), IMG_H - 1.f);

        int cf = t - 1;
        g_scores[cf * N_PROP + n] = prob;
        g_boxes[cf * N_PROP + n] = make_float4(x1, y1, x2, y2);
    }
}

// ---------------------------------------------------------------------------
// K2: per-class compaction + bitonic sort (score desc, idx asc) + greedy NMS.
// One block per foreground class.
// ---------------------------------------------------------------------------
__global__ void k2_nms() {
    const int NT = 256;
    int cf = blockIdx.x;
    int tid = threadIdx.x;

    __shared__ unsigned long long key[N_PROP];
    __shared__ float4 boxs[N_PROP];
    __shared__ unsigned char supp[N_PROP];
    __shared__ int cnt;

    if (tid == 0) cnt = 0;
    __syncthreads();

    // Compact: valid = score > 0.05. Valid entries occupy the leading ranks
    // of the full descending argsort (all invalid scores are strictly lower).
    for (int n = tid; n < N_PROP; n += NT) {
        float s = g_scores[cf * N_PROP + n];
        if (s > SCORE_THRESH) {
            int p = atomicAdd(&cnt, 1);
            // sort key: score desc primary, proposal idx asc secondary (stable)
            key[p] = ((unsigned long long)__float_as_uint(s) << 32)
                   | (unsigned long long)(0xFFFFFFFFu - (unsigned)n);
        }
    }
    __syncthreads();
    int c = cnt;
    if (c == 0) return;

    int M = 2;
    while (M < c) M <<= 1;
    for (int i = c + tid; i < M; i += NT) key[i] = 0ull;

    // Bitonic sort descending, M elements in shared.
    for (int k = 2; k <= M; k <<= 1) {
        for (int j = k >> 1; j > 0; j >>= 1) {
            __syncthreads();
            for (int i = tid; i < M; i += NT) {
                int ixj = i ^ j;
                if (ixj > i) {
                    unsigned long long a = key[i], b = key[ixj];
                    bool up = ((i & k) == 0);
                    if (up ? (a < b) : (a > b)) { key[i] = b; key[ixj] = a; }
                }
            }
        }
    }
    __syncthreads();

    // Gather boxes in sorted order.
    for (int i = tid; i < c; i += NT) {
        unsigned n = 0xFFFFFFFFu - (unsigned)(key[i] & 0xFFFFFFFFu);
        boxs[i] = g_boxes[cf * N_PROP + n];
        supp[i] = 0;
    }

    // Greedy NMS over sorted candidates (legacy +1 IoU, strict > threshold).
    for (int r = 0; r < c; ++r) {
        __syncthreads();
        if (supp[r]) continue;
        float4 pb = boxs[r];
        if (tid == 0) {
            int slot = atomicAdd(&g_keep_count, 1);
            if (slot < KEEP_CAP) {
                unsigned flat = (unsigned)(cf * N_PROP + r);  // < 2^17
                unsigned sb = (unsigned)(key[r] >> 32);
                // key: [63:32]=scorebits, [31:15]=(0x1FFFF-flat), [14:0]=slot
                g_keep_key[slot] = ((unsigned long long)sb << 32)
                                 | ((unsigned long long)(0x1FFFFu - flat) << 15)
                                 | (unsigned long long)(slot & 0x7FFF);
                g_keep_box[slot] = pb;
            }
        }
        float pa = (pb.z - pb.x + 1.f) * (pb.w - pb.y + 1.f);
        for (int j = r + 1 + tid; j < c; j += NT) {
            if (supp[j]) continue;
            float4 q = boxs[j];
            float qa = (q.z - q.x + 1.f) * (q.w - q.y + 1.f);
            float ix1 = fmaxf(pb.x, q.x), iy1 = fmaxf(pb.y, q.y);
            float ix2 = fminf(pb.z, q.z), iy2 = fminf(pb.w, q.w);
            float iw = fmaxf(ix2 - ix1 + 1.f, 0.f);
            float ih = fmaxf(iy2 - iy1 + 1.f, 0.f);
            float inter = iw * ih;
            float iou = inter / (pa + qa - inter);
            if (iou > NMS_THRESH) supp[j] = 1;
        }
    }
}

// ---------------------------------------------------------------------------
// K3: global top-100 over kept candidates; emit boxes/scores/labels.
// out layout: [0:400) boxes, [400:500) scores, [500:600) labels (as float).
// ---------------------------------------------------------------------------
__global__ void k3_topk(float* __restrict__ out) {
    const int NT = 512;
    int tid = threadIdx.x;
    __shared__ unsigned long long key[SORTN];

    int m = g_keep_count;
    if (m > SORTN) m = SORTN;
    int M = 128;
    while (M < m) M <<= 1;

    for (int i = tid; i < M; i += NT)
        key[i] = (i < m) ? g_keep_key[i] : 0ull;

    for (int k = 2; k <= M; k <<= 1) {
        for (int j = k >> 1; j > 0; j >>= 1) {
            __syncthreads();
            for (int i = tid; i < M; i += NT) {
                int ixj = i ^ j;
                if (ixj > i) {
                    unsigned long long a = key[i], b = key[ixj];
                    bool up = ((i & k) == 0);
                    if (up ? (a < b) : (a > b)) { key[i] = b; key[ixj] = a; }
                }
            }
        }
    }
    __syncthreads();

    if (tid < DET) {
        unsigned long long kk = key[tid];
        float score = __uint_as_float((unsigned)(kk >> 32));
        bool ok = score > 0.f;
        unsigned flat = 0x1FFFFu - (unsigned)((kk >> 15) & 0x1FFFFu);
        int slot = (int)(kk & 0x7FFFu);
        float4 b = make_float4(0.f, 0.f, 0.f, 0.f);
        if (ok) b = g_keep_box[slot];
        out[tid * 4 + 0] = b.x;
        out[tid * 4 + 1] = b.y;
        out[tid * 4 + 2] = b.z;
        out[tid * 4 + 3] = b.w;
        out[4 * DET + tid] = ok ? score : 0.f;
        out[5 * DET + tid] = ok ? (float)(flat / N_PROP + 1) : 0.f;
    }
}

extern "C" void kernel_launch(void* const* d_in, const int* in_sizes, int n_in,
                              void* d_out, int out_size) {
    const float* class_logits = (const float*)d_in[0];   // [1024, 81]
    const float* box_regression = (const float*)d_in[1]; // [1024, 324]
    const float* proposals = (const float*)d_in[2];      // [1024, 4]
    float* out = (float*)d_out;                          // 600 floats

    k1_decode<<<N_PROP, 128>>>(class_logits, box_regression, proposals);
    k2_nms<<<CF, 256>>>();
    k3_topk<<<1, 512>>>(out);
}

// round 2
// speedup vs baseline: 1.8959x; 1.8959x over previous
#include <cuda_runtime.h>
#include <math.h>

#define N_PROP 1024
#define C_ALL 81
#define CF 80
#define DET 100
#define SCORE_THRESH 0.05f
#define NMS_THRESH 0.5f
#define IMG_W 1333.0f
#define IMG_H 800.0f
#define KEEP_CAP 32768
#define SURV_CAP 4096

typedef unsigned long long ull;

// Scratch (allocation-free: __device__ globals)
__device__ float2 g_sminfo[N_PROP];   // (max_logit, 1/sum_exp)
__device__ float4 g_pinfo[N_PROP];    // (w, h, cx, cy)
__device__ ull    g_keep_key[KEEP_CAP];
__device__ float4 g_keep_box[KEEP_CAP];
__device__ int    g_keep_count;

// ---------------------------------------------------------------------------
// K0: per-proposal softmax denominator + proposal geometry. Warp per proposal.
// ---------------------------------------------------------------------------
__global__ void k0_prep(const float* __restrict__ logits,
                        const float* __restrict__ props) {
    int warp = threadIdx.x >> 5, lane = threadIdx.x & 31;
    int n = blockIdx.x * 8 + warp;
    if (blockIdx.x == 0 && threadIdx.x == 0) g_keep_count = 0;
    if (n >= N_PROP) return;

    const float* L = logits + n * C_ALL;
    float a = L[lane];                                   // lanes 0..31
    float b = L[lane + 32];                              // 32..63
    float c = (lane + 64 < C_ALL) ? L[lane + 64] : -1e30f;
    float mx = fmaxf(a, fmaxf(b, c));
    #pragma unroll
    for (int off = 16; off > 0; off >>= 1)
        mx = fmaxf(mx, __shfl_xor_sync(0xFFFFFFFFu, mx, off));
    float s = expf(a - mx) + expf(b - mx) + ((lane + 64 < C_ALL) ? expf(c - mx) : 0.f);
    #pragma unroll
    for (int off = 16; off > 0; off >>= 1)
        s += __shfl_xor_sync(0xFFFFFFFFu, s, off);

    if (lane == 0) {
        g_sminfo[n] = make_float2(mx, 1.0f / s);
        float4 p = ((const float4*)props)[n];
        float w = p.z - p.x + 1.0f, h = p.w - p.y + 1.0f;
        g_pinfo[n] = make_float4(w, h, p.x + 0.5f * w, p.y + 0.5f * h);
    }
}

// ---------------------------------------------------------------------------
// K1: per-class (80 blocks): compute probs, decode+clip boxes for valid ones,
// sort (score desc, idx asc), greedy NMS, append kept to global list.
// ---------------------------------------------------------------------------
__global__ void k1_nms(const float* __restrict__ logits,
                       const float* __restrict__ rel) {
    const int NT = 256;
    int cf = blockIdx.x;
    int cls = cf + 1;
    int tid = threadIdx.x;

    __shared__ ull key[N_PROP];
    __shared__ float4 tbox[N_PROP];      // by compact slot
    __shared__ float4 boxs[N_PROP];      // sorted order
    __shared__ unsigned char supp[N_PROP];
    __shared__ int cnt;

    if (tid == 0) cnt = 0;
    __syncthreads();

    const float CLIP = 4.135166556742356f;  // log(1000/16)
    for (int n = tid; n < N_PROP; n += NT) {
        float l = logits[n * C_ALL + cls];
        float2 sm = g_sminfo[n];
        float prob = expf(l - sm.x) * sm.y;
        if (prob > SCORE_THRESH) {
            float4 pi = g_pinfo[n];  // w,h,cx,cy
            float4 r4 = *(const float4*)(rel + n * (4 * C_ALL) + 4 * cls);
            float dx = r4.x * 0.1f;
            float dy = r4.y * 0.1f;
            float dw = fminf(r4.z * 0.2f, CLIP);
            float dh = fminf(r4.w * 0.2f, CLIP);
            float pcx = dx * pi.x + pi.z, pcy = dy * pi.y + pi.w;
            float pw = expf(dw) * pi.x, ph = expf(dh) * pi.y;
            float x1 = pcx - 0.5f * pw;
            float y1 = pcy - 0.5f * ph;
            float x2 = pcx + 0.5f * pw - 1.0f;
            float y2 = pcy + 0.5f * ph - 1.0f;
            x1 = fminf(fmaxf(x1, 0.f), IMG_W - 1.f);
            x2 = fminf(fmaxf(x2, 0.f), IMG_W - 1.f);
            y1 = fminf(fmaxf(y1, 0.f), IMG_H - 1.f);
            y2 = fminf(fmaxf(y2, 0.f), IMG_H - 1.f);
            int p = atomicAdd(&cnt, 1);
            tbox[p] = make_float4(x1, y1, x2, y2);
            // key: [63:32]=scorebits, [19:10]=(1023-n) (idx asc on ties), [9:0]=slot
            key[p] = ((ull)__float_as_uint(prob) << 32)
                   | ((ull)(unsigned)(1023 - n) << 10)
                   | (ull)(unsigned)p;
        }
    }
    __syncthreads();
    int c = cnt;
    if (c == 0) return;

    int M = 32;
    while (M < c) M <<= 1;
    for (int i = c + tid; i < M; i += NT) key[i] = 0ull;

    // Bitonic sort descending (M <= 1024, typically 32/64)
    for (int k = 2; k <= M; k <<= 1) {
        for (int j = k >> 1; j > 0; j >>= 1) {
            __syncthreads();
            for (int i = tid; i < M; i += NT) {
                int ixj = i ^ j;
                if (ixj > i) {
                    ull a = key[i], b = key[ixj];
                    bool up = ((i & k) == 0);
                    if (up ? (a < b) : (a > b)) { key[i] = b; key[ixj] = a; }
                }
            }
        }
    }
    __syncthreads();

    for (int i = tid; i < c; i += NT) {
        boxs[i] = tbox[key[i] & 0x3FFu];
        supp[i] = 0;
    }

    // Greedy NMS (legacy +1 IoU, strict > threshold)
    for (int r = 0; r < c; ++r) {
        __syncthreads();
        if (supp[r]) continue;
        float4 pb = boxs[r];
        if (tid == 0) {
            int slot = atomicAdd(&g_keep_count, 1);
            if (slot < KEEP_CAP) {
                unsigned flat = (unsigned)(cf * N_PROP + r);   // < 2^17
                unsigned sb = (unsigned)(key[r] >> 32);
                // kept key: [63:32]=scorebits, [31:15]=(0x1FFFF-flat), [14:0]=slot
                g_keep_key[slot] = ((ull)sb << 32)
                                 | ((ull)(0x1FFFFu - flat) << 15)
                                 | (ull)(slot & 0x7FFF);
                g_keep_box[slot] = pb;
            }
        }
        float pa = (pb.z - pb.x + 1.f) * (pb.w - pb.y + 1.f);
        for (int j = r + 1 + tid; j < c; j += NT) {
            if (supp[j]) continue;
            float4 q = boxs[j];
            float qa = (q.z - q.x + 1.f) * (q.w - q.y + 1.f);
            float ix1 = fmaxf(pb.x, q.x), iy1 = fmaxf(pb.y, q.y);
            float ix2 = fminf(pb.z, q.z), iy2 = fminf(pb.w, q.w);
            float iw = fmaxf(ix2 - ix1 + 1.f, 0.f);
            float ih = fmaxf(iy2 - iy1 + 1.f, 0.f);
            float inter = iw * ih;
            float iou = inter / (pa + qa - inter);
            if (iou > NMS_THRESH) supp[j] = 1;
        }
    }
}

// ---------------------------------------------------------------------------
// K2: exact top-100 by histogram threshold + rank counting (no sort network).
// out layout: [0:400) boxes, [400:500) scores, [500:600) labels (as float).
// ---------------------------------------------------------------------------
__global__ void k2_topk(float* __restrict__ out) {
    const int NT = 512;
    int tid = threadIdx.x;
    __shared__ int hist[2048];
    __shared__ ull S[SURV_CAP];
    __shared__ int s_cnt;
    __shared__ int s_bstar;

    int m = g_keep_count;
    if (m > KEEP_CAP) m = KEEP_CAP;

    // zero outputs (poisoned by harness)
    for (int i = tid; i < 6 * DET; i += NT) out[i] = 0.f;
    for (int i = tid; i < 2048; i += NT) hist[i] = 0;
    if (tid == 0) { s_cnt = 0; s_bstar = 0; }
    __syncthreads();

    // 12-bit monotone bucket = top bits of key (sign=0, exp8, mant3) -> <2048
    for (int i = tid; i < m; i += NT)
        atomicAdd(&hist[(unsigned)(g_keep_key[i] >> 52)], 1);
    __syncthreads();

    // warp 0: find bucket of the DET-th largest key (b*), scanning high->low
    if (tid < 32) {
        int lane = tid;
        int base = lane * 64;
        int cs = 0;
        for (int j = 0; j < 64; ++j) cs += hist[base + j];
        int suf = cs;  // inclusive suffix over lanes >= lane
        #pragma unroll
        for (int off = 1; off < 32; off <<= 1) {
            int v = __shfl_down_sync(0xFFFFFFFFu, suf, off);
            if (lane + off < 32) suf += v;
        }
        int sufExcl = suf - cs;   // keys in buckets >= (lane+1)*64
        if (sufExcl < DET && suf >= DET) {   // crossing chunk (at most one lane)
            int cum = sufExcl;
            for (int b = base + 63; b >= base; --b) {
                cum += hist[b];
                if (cum >= DET) { s_bstar = b; break; }
            }
        }
        // if total < DET no lane crosses; s_bstar stays 0 (all survive)
    }
    __syncthreads();
    unsigned bstar = (unsigned)s_bstar;

    // compact survivors (bucket >= b*); all non-survivors have strictly smaller keys
    for (int i = tid; i < m; i += NT) {
        ull k = g_keep_key[i];
        if ((unsigned)(k >> 52) >= bstar) {
            int p = atomicAdd(&s_cnt, 1);
            if (p < SURV_CAP) S[p] = k;
        }
    }
    __syncthreads();
    int sc = s_cnt;
    if (sc > SURV_CAP) sc = SURV_CAP;

    // exact rank of each survivor among survivors == global rank
    ull mine[8];
    int rank[8];
    int own = 0;
    for (int i = tid; i < sc; i += NT) { mine[own] = S[i]; rank[own] = 0; own++; }
    __syncthreads();
    for (int j = 0; j < sc; ++j) {
        ull v = S[j];                 // broadcast read
        #pragma unroll
        for (int q = 0; q < 8; ++q)
            if (q < own) rank[q] += (v > mine[q]);
    }

    #pragma unroll
    for (int q = 0; q < 8; ++q) {
        if (q < own && rank[q] < DET) {
            int r = rank[q];
            ull kk = mine[q];
            float score = __uint_as_float((unsigned)(kk >> 32));
            unsigned flat = 0x1FFFFu - (unsigned)((kk >> 15) & 0x1FFFFu);
            int slot = (int)(kk & 0x7FFFu);
            float4 b = g_keep_box[slot];
            out[r * 4 + 0] = b.x;
            out[r * 4 + 1] = b.y;
            out[r * 4 + 2] = b.z;
            out[r * 4 + 3] = b.w;
            out[4 * DET + r] = score;
            out[5 * DET + r] = (float)(flat / N_PROP + 1);
        }
    }
}

extern "C" void kernel_launch(void* const* d_in, const int* in_sizes, int n_in,
                              void* d_out, int out_size) {
    const float* class_logits = (const float*)d_in[0];   // [1024, 81]
    const float* box_regression = (const float*)d_in[1]; // [1024, 324]
    const float* proposals = (const float*)d_in[2];      // [1024, 4]
    float* out = (float*)d_out;                          // 600 floats

    k0_prep<<<N_PROP / 8, 256>>>(class_logits, proposals);
    k1_nms<<<CF, 256>>>(class_logits, box_regression);
    k2_topk<<<1, 512>>>(out);
}